// round 13
// baseline (speedup 1.0000x reference)
#include <cuda_runtime.h>
#include <math.h>
#include <float.h>

// Problem constants
#define B_DIM 32
#define C_DIM 9
#define T_DIM 4096
#define NROWS (B_DIM * T_DIM)          // 131072
#define QTR (NROWS / 4)                // 32768
#define NCODES 512
#define CODE_DIM 64
#define HALF_DIM 32
#define PDIM 12                        // 11 feature dims + bias
#define PSTRIDE 13                     // padded stride for fixup smem table
#define DROW (PDIM * 2)                // 24 floats per code (lane-duplicated)
#define SCORE_SHIFT 32.0f
#define FIX_THR 3e-4f                  // raw fp32 gap threshold (fp32 err ~5e-5)

#define IDX_OFF (NROWS * CODE_DIM)     // 8388608
#define PH_OFF (IDX_OFF + NROWS)       // 8519680

// Scratch (no cudaMalloc allowed)
__device__ float  g_phase_scratch[B_DIM * C_DIM * T_DIM];
__device__ float  g_p32d[NCODES * DROW];     // lane-duplicated fp32 (shifted bias)
__device__ float  g_p32s[NCODES * PSTRIDE];  // compact padded fp32 (shifted bias)
__device__ double g_p64[NCODES * PDIM];      // exact (unshifted)
__device__ int    g_fix_count;
__device__ int    g_fix_list[NROWS];

// ---------------------------------------------------------------------------
// FFT helpers (radix-4, 4096 = 4^6)
// ---------------------------------------------------------------------------
__device__ __forceinline__ float2 cmul(float2 a, float2 b) {
    return make_float2(fmaf(a.x, b.x, -a.y * b.y), fmaf(a.x, b.y, a.y * b.x));
}

// DIT stages [sstart..5]: digit-reversed input -> natural output.
__device__ void fft4096_r4_dit(float2* __restrict__ buf,
                               const float2* __restrict__ tw, int tid, int sstart) {
    #pragma unroll 1
    for (int s = sstart; s < 6; s++) {
        int quarter = 1 << (2 * s);
        int rstep   = 1024 >> (2 * s);
        #pragma unroll
        for (int q = tid; q < 1024; q += 512) {
            int j   = q & (quarter - 1);
            int grp = q >> (2 * s);
            int pos = grp * (quarter << 2) + j;

            float2 w1 = tw[j * rstep];
            float2 w2 = cmul(w1, w1);
            float2 w3 = cmul(w2, w1);

            float2 a0 = buf[pos];
            float2 a1 = cmul(buf[pos + quarter],     w1);
            float2 a2 = cmul(buf[pos + 2 * quarter], w2);
            float2 a3 = cmul(buf[pos + 3 * quarter], w3);

            float2 t0 = make_float2(a0.x + a2.x, a0.y + a2.y);
            float2 t1 = make_float2(a0.x - a2.x, a0.y - a2.y);
            float2 t2 = make_float2(a1.x + a3.x, a1.y + a3.y);
            float2 t3 = make_float2(a1.x - a3.x, a1.y - a3.y);

            buf[pos]               = make_float2(t0.x + t2.x, t0.y + t2.y);
            buf[pos + quarter]     = make_float2(t1.x + t3.y, t1.y - t3.x);
            buf[pos + 2 * quarter] = make_float2(t0.x - t2.x, t0.y - t2.y);
            buf[pos + 3 * quarter] = make_float2(t1.x - t3.y, t1.y + t3.x);
        }
        __syncthreads();
    }
}

// DIF: natural input -> digit-reversed output.
__device__ void fft4096_r4_dif(float2* __restrict__ buf,
                               const float2* __restrict__ tw, int tid) {
    #pragma unroll 1
    for (int s = 0; s < 6; s++) {
        int quarter = 1024 >> (2 * s);
        int tstep   = 1 << (2 * s);
        int shift   = 10 - 2 * s;
        #pragma unroll
        for (int q = tid; q < 1024; q += 512) {
            int j   = q & (quarter - 1);
            int grp = q >> shift;
            int pos = grp * (quarter << 2) + j;

            float2 a0 = buf[pos];
            float2 a1 = buf[pos + quarter];
            float2 a2 = buf[pos + 2 * quarter];
            float2 a3 = buf[pos + 3 * quarter];

            float2 t0 = make_float2(a0.x + a2.x, a0.y + a2.y);
            float2 t1 = make_float2(a0.x - a2.x, a0.y - a2.y);
            float2 t2 = make_float2(a1.x + a3.x, a1.y + a3.y);
            float2 t3 = make_float2(a1.x - a3.x, a1.y - a3.y);

            float2 b0 = make_float2(t0.x + t2.x, t0.y + t2.y);
            float2 b1 = make_float2(t1.x + t3.y, t1.y - t3.x);
            float2 b2 = make_float2(t0.x - t2.x, t0.y - t2.y);
            float2 b3 = make_float2(t1.x - t3.y, t1.y + t3.x);

            float2 w1 = tw[j * tstep];
            float2 w2 = cmul(w1, w1);
            float2 w3 = cmul(w2, w1);

            buf[pos]               = b0;
            buf[pos + quarter]     = cmul(b1, w1);
            buf[pos + 2 * quarter] = cmul(b2, w2);
            buf[pos + 3 * quarter] = cmul(b3, w3);
        }
        __syncthreads();
    }
}

// ---------------------------------------------------------------------------
// Kernel 1: analytic-signal phase. DIF fwd; Hilbert*conj fused into DIT
// stage 0; DIT stages 1..5; atan2.
// ---------------------------------------------------------------------------
__global__ void phase_kernel(const float* __restrict__ imu) {
    extern __shared__ float2 sm[];
    float2* buf = sm;          // 4096
    float2* tw  = sm + 4096;   // 1024

    int tid = threadIdx.x;
    int bc  = blockIdx.x;      // 0..287

    for (int k = tid; k < 1024; k += 512) {
        float sv, cv;
        sincospif(-(float)k * (1.0f / 2048.0f), &sv, &cv);
        tw[k] = make_float2(cv, sv);
    }

    const float* x = imu + (size_t)bc * T_DIM;
    for (int i = tid; i < 4096; i += 512) {
        buf[i] = make_float2(x[i], 0.0f);
    }
    __syncthreads();

    fft4096_r4_dif(buf, tw, tid);

    // Fused Hilbert + conj + DIT stage 0
    for (int g = tid; g < 1024; g += 512) {
        int pos = g * 4;
        float2 x0 = buf[pos];
        float2 x1 = buf[pos + 1];
        float2 a1 = make_float2(2.0f * x1.x, -2.0f * x1.y);
        float2 t0, t1;
        if (g == 0) {
            float2 x2 = buf[2];
            float2 a0 = make_float2(x0.x, -x0.y);
            float2 a2 = make_float2(x2.x, -x2.y);
            t0 = make_float2(a0.x + a2.x, a0.y + a2.y);
            t1 = make_float2(a0.x - a2.x, a0.y - a2.y);
        } else {
            float2 a0 = make_float2(2.0f * x0.x, -2.0f * x0.y);
            t0 = a0;
            t1 = a0;
        }
        buf[pos]     = make_float2(t0.x + a1.x, t0.y + a1.y);
        buf[pos + 1] = make_float2(t1.x + a1.y, t1.y - a1.x);
        buf[pos + 2] = make_float2(t0.x - a1.x, t0.y - a1.y);
        buf[pos + 3] = make_float2(t1.x - a1.y, t1.y + a1.x);
    }
    __syncthreads();

    fft4096_r4_dit(buf, tw, tid, 1);

    float* dst = g_phase_scratch + (size_t)bc * T_DIM;
    for (int i = tid; i < 4096; i += 512) {
        float2 z = buf[i];
        dst[i] = atan2f(-z.y, z.x);
    }
}

// ---------------------------------------------------------------------------
// Kernel 2: precompute per-code projected 12-dim tables
// ---------------------------------------------------------------------------
__device__ __forceinline__ double warp_sum_d(double v) {
    #pragma unroll
    for (int m = 16; m > 0; m >>= 1) v += __shfl_xor_sync(0xFFFFFFFFu, v, m);
    return v;
}

__global__ void precompute_kernel(const float* __restrict__ W_mag,
                                  const float* __restrict__ b_mag,
                                  const float* __restrict__ W_phase,
                                  const float* __restrict__ b_phase,
                                  const float* __restrict__ codebook) {
    int k = blockIdx.x;
    int d = threadIdx.x;     // 0..31
    const float* c = codebook + k * CODE_DIM;

    if (k == 0 && d == 0) g_fix_count = 0;

    double cm = (double)c[d];
    double cp = (double)c[HALF_DIM + d];

    double u[9], v[9];
    #pragma unroll
    for (int i = 0; i < 9; i++) {
        u[i] = (double)W_mag[d * 9 + i] * cm;
        v[i] = (double)W_phase[d * 9 + i] * cp;
    }
    double w = (double)b_mag[d] * cm + (double)b_phase[d] * cp
             - 0.5 * (cm * cm + cp * cp);

    double p[PDIM];
    #pragma unroll
    for (int i = 0; i < 7; i++) p[i] = warp_sum_d(u[i] + v[i]);
    p[7]  = warp_sum_d(u[7]);
    p[8]  = warp_sum_d(u[8]);
    p[9]  = warp_sum_d(v[7]);
    p[10] = warp_sum_d(v[8]);
    p[11] = warp_sum_d(w);

    if (d == 0) {
        #pragma unroll
        for (int i = 0; i < PDIM; i++) {
            g_p64[k * PDIM + i] = p[i];
            float f = (float)p[i];
            if (i == 11) f = (float)(p[i] + (double)SCORE_SHIFT);
            g_p32s[k * PSTRIDE + i] = f;
            g_p32d[k * DROW + i * 2]     = f;
            g_p32d[k * DROW + i * 2 + 1] = f;
        }
    }
}

// ---------------------------------------------------------------------------
// Kernel 3: argmax; 4 rows per thread (two f32x2 accumulator chains).
// Broadcast smem reads; raw-score setp/sel tracking (no index embed);
// fp32-exact gap -> tight 3e-4 fixup threshold.
// ---------------------------------------------------------------------------
__device__ __forceinline__ unsigned long long pack2(float lo, float hi) {
    unsigned long long r;
    asm("mov.b64 %0, {%1, %2};" : "=l"(r) : "f"(lo), "f"(hi));
    return r;
}
__device__ __forceinline__ void unpack2(unsigned long long v, float& lo, float& hi) {
    asm("mov.b64 {%0, %1}, %2;" : "=f"(lo), "=f"(hi) : "l"(v));
}
__device__ __forceinline__ unsigned long long fma2(unsigned long long a,
                                                   unsigned long long b,
                                                   unsigned long long c) {
    unsigned long long d;
    asm("fma.rn.f32x2 %0, %1, %2, %3;" : "=l"(d) : "l"(a), "l"(b), "l"(c));
    return d;
}

__device__ __forceinline__ void load_features(const float* __restrict__ imu,
                                              int row, float* g, float& ph) {
    int b = row >> 12;
    int t = row & 4095;
    const float* phbase = g_phase_scratch + (size_t)(b * C_DIM) * T_DIM + t;
    float s = 0.0f;
    #pragma unroll
    for (int c = 0; c < 9; c++) s += phbase[(size_t)c * T_DIM];
    ph = s * (1.0f / 9.0f);
    const float* ib = imu + (size_t)(b * C_DIM) * T_DIM + t;
    #pragma unroll
    for (int c = 0; c < 9; c++) g[c] = ib[(size_t)c * T_DIM];
    g[9]  = cosf(ph);
    g[10] = sinf(ph);
}

__global__ void __launch_bounds__(256) quantize_kernel(
    const float* __restrict__ imu,
    const float* __restrict__ codebook,
    float* __restrict__ out) {

    __shared__ __align__(16) float sp[NCODES * DROW];   // 48 KB
    int tid = threadIdx.x;
    {
        const float4* src = (const float4*)g_p32d;
        float4* dst = (float4*)sp;
        for (int i = tid; i < NCODES * DROW / 4; i += 256) dst[i] = src[i];
    }
    __syncthreads();

    int gid = blockIdx.x * 256 + tid;    // 0..32767
    int rows[4];
    #pragma unroll
    for (int r = 0; r < 4; r++) rows[r] = gid + r * QTR;

    float g0[11], g1[11], g2[11], g3[11], ph[4];
    load_features(imu, rows[0], g0, ph[0]);
    load_features(imu, rows[1], g1, ph[1]);
    load_features(imu, rows[2], g2, ph[2]);
    load_features(imu, rows[3], g3, ph[3]);

    unsigned long long gpA[11], gpB[11];
    #pragma unroll
    for (int i = 0; i < 11; i++) {
        gpA[i] = pack2(g0[i], g1[i]);
        gpB[i] = pack2(g2[i], g3[i]);
    }

    float best[4], b2[4];
    int bidx[4];
    #pragma unroll
    for (int r = 0; r < 4; r++) { best[r] = -FLT_MAX; b2[r] = -FLT_MAX; bidx[r] = 0; }

    #pragma unroll 4
    for (int jj = 0; jj < NCODES; jj++) {
        const ulonglong2* pr = (const ulonglong2*)(sp + jj * DROW);  // broadcast
        ulonglong2 v0 = pr[0], v1 = pr[1], v2 = pr[2];
        ulonglong2 v3 = pr[3], v4 = pr[4], v5 = pr[5];
        unsigned long long aA = v5.y, aB = v5.y;
        aA = fma2(gpA[0],  v0.x, aA);  aB = fma2(gpB[0],  v0.x, aB);
        aA = fma2(gpA[1],  v0.y, aA);  aB = fma2(gpB[1],  v0.y, aB);
        aA = fma2(gpA[2],  v1.x, aA);  aB = fma2(gpB[2],  v1.x, aB);
        aA = fma2(gpA[3],  v1.y, aA);  aB = fma2(gpB[3],  v1.y, aB);
        aA = fma2(gpA[4],  v2.x, aA);  aB = fma2(gpB[4],  v2.x, aB);
        aA = fma2(gpA[5],  v2.y, aA);  aB = fma2(gpB[5],  v2.y, aB);
        aA = fma2(gpA[6],  v3.x, aA);  aB = fma2(gpB[6],  v3.x, aB);
        aA = fma2(gpA[7],  v3.y, aA);  aB = fma2(gpB[7],  v3.y, aB);
        aA = fma2(gpA[8],  v4.x, aA);  aB = fma2(gpB[8],  v4.x, aB);
        aA = fma2(gpA[9],  v4.y, aA);  aB = fma2(gpB[9],  v4.y, aB);
        aA = fma2(gpA[10], v5.x, aA);  aB = fma2(gpB[10], v5.x, aB);
        float s[4];
        unpack2(aA, s[0], s[1]);
        unpack2(aB, s[2], s[3]);
        #pragma unroll
        for (int r = 0; r < 4; r++) {
            float tmin = fminf(s[r], best[r]);
            b2[r] = fmaxf(b2[r], tmin);
            bool c = s[r] > best[r];         // strict > keeps lowest index
            best[r] = fmaxf(best[r], s[r]);
            bidx[r] = c ? jj : bidx[r];
        }
    }

    #pragma unroll
    for (int r = 0; r < 4; r++) {
        int row = rows[r];
        out[IDX_OFF + row] = (float)bidx[r];
        out[PH_OFF + row] = ph[r];
        if (best[r] - b2[r] < FIX_THR) {
            int slot = atomicAdd(&g_fix_count, 1);
            g_fix_list[slot] = row;
        }
    }

    // Warp-cooperative coalesced gather per quarter
    int lane = tid & 31;
    const float4* cb4 = (const float4*)codebook;
    float4* o4 = (float4*)out;
    #pragma unroll
    for (int r = 0; r < 4; r++) {
        int wrow = (gid & ~31) + r * QTR;
        #pragma unroll
        for (int i = 0; i < 16; i++) {
            int f = i * 32 + lane;          // 0..511 float4s in warp region
            int rsel = f >> 4;              // row-within-warp 0..31
            int col  = f & 15;
            int bs = __shfl_sync(0xFFFFFFFFu, bidx[r], rsel);
            o4[(size_t)(wrow + rsel) * 16 + col] = cb4[bs * 16 + col];
        }
    }
}

// ---------------------------------------------------------------------------
// Kernel 4: exact rerank for flagged rows (few now). One warp per row:
// fp32 pass from smem, fp64 only for candidates within 1e-3 of warp max.
// ---------------------------------------------------------------------------
__global__ void __launch_bounds__(256) fixup_kernel(
    const float* __restrict__ imu,
    const float* __restrict__ codebook,
    float* __restrict__ out) {

    int n = g_fix_count;
    if (blockIdx.x * 8 >= n) return;

    __shared__ float st[NCODES * PSTRIDE];   // 26 KB
    int tid = threadIdx.x;
    for (int i = tid; i < NCODES * PSTRIDE; i += 256) st[i] = g_p32s[i];
    __syncthreads();

    int lane = tid & 31;
    int warp = (blockIdx.x * blockDim.x + tid) >> 5;
    int nwarps = (gridDim.x * blockDim.x) >> 5;

    for (int i = warp; i < n; i += nwarps) {
        int row = g_fix_list[i];
        float gf[11], ph;
        load_features(imu, row, gf, ph);

        // pass 1: fp32 scores from smem (two independent chains for ILP)
        float sc[16];
        float lbest = -FLT_MAX;
        #pragma unroll
        for (int c = 0; c < 16; c += 2) {
            const float* pr0 = st + ((c)     * 32 + lane) * PSTRIDE;
            const float* pr1 = st + ((c + 1) * 32 + lane) * PSTRIDE;
            float sa = pr0[11];
            float sb = pr1[11];
            #pragma unroll
            for (int k = 0; k < 11; k++) {
                sa = fmaf(gf[k], pr0[k], sa);
                sb = fmaf(gf[k], pr1[k], sb);
            }
            sc[c] = sa;
            sc[c + 1] = sb;
            lbest = fmaxf(lbest, fmaxf(sa, sb));
        }
        #pragma unroll
        for (int m = 16; m > 0; m >>= 1)
            lbest = fmaxf(lbest, __shfl_xor_sync(0xFFFFFFFFu, lbest, m));
        float thr = lbest - 1e-3f;

        // pass 2: fp64 for candidates only
        double gd[11];
        #pragma unroll
        for (int k = 0; k < 11; k++) gd[k] = (double)gf[k];
        double bd = -1.0e300;
        int bi = NCODES;
        #pragma unroll 1
        for (int c = 0; c < 16; c++) {
            if (sc[c] >= thr) {
                int j = c * 32 + lane;
                const double* pr = g_p64 + j * PDIM;
                double s0 = pr[11];
                double s1 = 0.0;
                #pragma unroll
                for (int k = 0; k < 10; k += 2) {
                    s0 += gd[k]     * pr[k];
                    s1 += gd[k + 1] * pr[k + 1];
                }
                s0 += gd[10] * pr[10];
                double s = s0 + s1;
                if (s > bd || (s == bd && j < bi)) { bd = s; bi = j; }
            }
        }
        #pragma unroll
        for (int m = 16; m > 0; m >>= 1) {
            double od = __shfl_xor_sync(0xFFFFFFFFu, bd, m);
            int    oi = __shfl_xor_sync(0xFFFFFFFFu, bi, m);
            if (od > bd || (od == bd && oi < bi)) { bd = od; bi = oi; }
        }
        if (lane == 0) out[IDX_OFF + row] = (float)bi;
        if (lane < 16) {
            const float4* cb = (const float4*)(codebook + (size_t)bi * CODE_DIM);
            float4* oq = (float4*)(out + (size_t)row * CODE_DIM);
            oq[lane] = cb[lane];
        }
    }
}

// ---------------------------------------------------------------------------
extern "C" void kernel_launch(void* const* d_in, const int* in_sizes, int n_in,
                              void* d_out, int out_size) {
    const float* imu      = (const float*)d_in[0];
    const float* W_mag    = (const float*)d_in[1];
    const float* b_mag    = (const float*)d_in[2];
    const float* W_phase  = (const float*)d_in[3];
    const float* b_phase  = (const float*)d_in[4];
    const float* codebook = (const float*)d_in[5];
    float* out = (float*)d_out;

    phase_kernel<<<B_DIM * C_DIM, 512, 5120 * sizeof(float2)>>>(imu);
    precompute_kernel<<<NCODES, 32>>>(W_mag, b_mag, W_phase, b_phase, codebook);
    quantize_kernel<<<QTR / 256, 256>>>(imu, codebook, out);
    fixup_kernel<<<296, 256>>>(imu, codebook, out);
}